// round 3
// baseline (speedup 1.0000x reference)
#include <cuda_runtime.h>
#include <math.h>

#define TT 1000
#define BB 256
#define II 128
#define NN 512
#define BN (BB * NN)
#define ALPHA_C 0.2f

#define GROUPS 8      // batch groups of 32 rows
#define SLICES 16     // N slices of 32 cols
#define PADW 36       // padded row stride (floats) for smem tiles
#define SMEM_BYTES (2 * 512 * PADW * 4)

// Per-group monotonic arrival counters; reset by xproj kernel each replay.
__device__ unsigned int g_bar[GROUPS];

typedef unsigned long long u64;

__device__ __forceinline__ u64 pk2(float x, float y) {
    u64 r; asm("mov.b64 %0, {%1, %2};" : "=l"(r) : "f"(x), "f"(y)); return r;
}
__device__ __forceinline__ float2 upk(u64 v) {
    float2 f; asm("mov.b64 {%0, %1}, %2;" : "=f"(f.x), "=f"(f.y) : "l"(v)); return f;
}
__device__ __forceinline__ u64 fma2(u64 a, u64 b, u64 c) {
    u64 r; asm("fma.rn.f32x2 %0, %1, %2, %3;" : "=l"(r) : "l"(a), "l"(b), "l"(c)); return r;
}

// ---------------------------------------------------------------------------
// Kernel A: xproj[m, n] = sum_i x[m, i] * W_in[n, i] + b_in[n]
// Written straight into out[t] slots. Also resets g_bar for the replay.
// ---------------------------------------------------------------------------
__global__ __launch_bounds__(256) void xproj_kernel(
    const float* __restrict__ X, const float* __restrict__ Win,
    const float* __restrict__ bin, float* __restrict__ C)
{
    if (blockIdx.x == 0 && blockIdx.y == 0 && threadIdx.x < GROUPS)
        g_bar[threadIdx.x] = 0;

    __shared__ float As[16 * 64];
    __shared__ float Bs[16 * 64];

    const int mBase = blockIdx.y * 64;
    const int nBase = blockIdx.x * 64;
    const int tid = threadIdx.x;
    const int lrow = tid >> 2;           // 0..63
    const int lcol = (tid & 3) << 2;     // 0,4,8,12
    const float* Ap = X + (size_t)(mBase + lrow) * II + lcol;
    const float* Bp = Win + (size_t)(nBase + lrow) * II + lcol;

    const int trow = (tid >> 4) << 2;
    const int tcol = (tid & 15) << 2;

    float acc[4][4];
    #pragma unroll
    for (int i = 0; i < 4; i++)
        #pragma unroll
        for (int j = 0; j < 4; j++) acc[i][j] = 0.0f;

    for (int k0 = 0; k0 < II; k0 += 16) {
        float4 a4 = *(const float4*)(Ap + k0);
        float4 b4 = *(const float4*)(Bp + k0);
        As[(lcol + 0) * 64 + lrow] = a4.x;
        As[(lcol + 1) * 64 + lrow] = a4.y;
        As[(lcol + 2) * 64 + lrow] = a4.z;
        As[(lcol + 3) * 64 + lrow] = a4.w;
        Bs[(lcol + 0) * 64 + lrow] = b4.x;
        Bs[(lcol + 1) * 64 + lrow] = b4.y;
        Bs[(lcol + 2) * 64 + lrow] = b4.z;
        Bs[(lcol + 3) * 64 + lrow] = b4.w;
        __syncthreads();
        #pragma unroll
        for (int kk = 0; kk < 16; kk++) {
            float4 ra4 = *(const float4*)&As[kk * 64 + trow];
            float4 rb4 = *(const float4*)&Bs[kk * 64 + tcol];
            float ra[4] = {ra4.x, ra4.y, ra4.z, ra4.w};
            float rb[4] = {rb4.x, rb4.y, rb4.z, rb4.w};
            #pragma unroll
            for (int i = 0; i < 4; i++)
                #pragma unroll
                for (int j = 0; j < 4; j++)
                    acc[i][j] += ra[i] * rb[j];
        }
        __syncthreads();
    }

    float4 bv = *(const float4*)&bin[nBase + tcol];
    float bvals[4] = {bv.x, bv.y, bv.z, bv.w};
    #pragma unroll
    for (int i = 0; i < 4; i++) {
        float4 o;
        o.x = acc[i][0] + bvals[0];
        o.y = acc[i][1] + bvals[1];
        o.z = acc[i][2] + bvals[2];
        o.w = acc[i][3] + bvals[3];
        *(float4*)&C[(size_t)(mBase + trow + i) * NN + nBase + tcol] = o;
    }
}

// ---------------------------------------------------------------------------
// Persistent recurrence kernel. 128 CTAs = 8 batch-groups x 16 N-slices.
// CTA tile: 32 batch rows x 32 N cols, all 1000 steps.
//   smem ws[512][PADW]: W_hh slice (cols nBase..nBase+31), k-major, loaded once
//   smem hs[512][PADW]: h_{t-1} rows (bBase..bBase+31), k-major, staged per step
// Thread tile: 2 rows x 4 cols via packed fma.rn.f32x2.
// Group barrier: monotonic counter, target 16*(t+1).
// ---------------------------------------------------------------------------
__global__ __launch_bounds__(128) void rnn_persistent(
    const float* __restrict__ h0, const float* __restrict__ Whh,
    float* __restrict__ out)
{
    extern __shared__ float sm[];
    float* ws = sm;               // [512][PADW]
    float* hs = sm + 512 * PADW;  // [512][PADW]

    const int cta = blockIdx.x;
    const int bg = cta >> 4;            // batch group 0..7
    const int ns = cta & 15;            // N slice 0..15
    const int bBase = bg * 32;
    const int nBase = ns * 32;
    const int tid = threadIdx.x;        // 0..127

    const int rp = tid >> 3;            // 0..15 -> rows 2rp, 2rp+1
    const int nq = tid & 7;             // 0..7  -> cols 4nq..4nq+3
    const int r0 = rp * 2;
    const int c0 = nq * 4;

    // --- one-time W_hh slice load: ws[k*PADW + n] = Whh[(nBase+n)*512 + k]
    for (int idx = tid; idx < 32 * 512; idx += 128) {
        int n = idx >> 9;
        int k = idx & 511;
        ws[k * PADW + n] = Whh[(size_t)(nBase + n) * NN + k];
    }
    __syncthreads();

    // staging thread mapping: 4 threads per row, 16-float chunks
    const int srow = tid >> 2;          // 0..31
    const int skt = (tid & 3) << 2;     // 0,4,8,12

    for (int t = 0; t < TT; t++) {
        // --- stage h_{t-1} rows into hs (k-major), L2 loads (bypass stale L1)
        const float* src = (t == 0) ? (h0 + (size_t)bBase * NN)
                                    : (out + (size_t)(t - 1) * BN + (size_t)bBase * NN);
        #pragma unroll 4
        for (int j = 0; j < 512; j += 16) {
            float4 v = __ldcg((const float4*)(src + (size_t)srow * NN + skt + j));
            hs[(skt + j + 0) * PADW + srow] = v.x;
            hs[(skt + j + 1) * PADW + srow] = v.y;
            hs[(skt + j + 2) * PADW + srow] = v.z;
            hs[(skt + j + 3) * PADW + srow] = v.w;
        }
        __syncthreads();

        // --- GEMM: acc[2 rows][4 cols] over K=512, packed f32x2 FMA
        u64 acc00 = 0, acc01 = 0, acc10 = 0, acc11 = 0;
        #pragma unroll 8
        for (int k = 0; k < 512; k++) {
            u64 a = *(const u64*)&hs[k * PADW + r0];               // rows r0, r0+1
            ulonglong2 b = *(const ulonglong2*)&ws[k * PADW + c0]; // cols c0..c0+3
            float2 af = upk(a);
            u64 axx = pk2(af.x, af.x);
            u64 ayy = pk2(af.y, af.y);
            acc00 = fma2(axx, b.x, acc00);
            acc01 = fma2(axx, b.y, acc01);
            acc10 = fma2(ayy, b.x, acc10);
            acc11 = fma2(ayy, b.y, acc11);
        }

        // --- epilogue: h = 0.8*hprev + 0.2*tanh(xp + acc)
        float2 p00 = upk(acc00), p01 = upk(acc01);
        float2 p10 = upk(acc10), p11 = upk(acc11);

        float* dst = out + (size_t)t * BN + (size_t)(bBase + r0) * NN + nBase + c0;
        float4 xp0 = *(const float4*)dst;
        float4 xp1 = *(const float4*)(dst + NN);

        // hprev from hs (k index = global column)
        float hp00 = hs[(nBase + c0 + 0) * PADW + r0];
        float hp01 = hs[(nBase + c0 + 1) * PADW + r0];
        float hp02 = hs[(nBase + c0 + 2) * PADW + r0];
        float hp03 = hs[(nBase + c0 + 3) * PADW + r0];
        float hp10 = hs[(nBase + c0 + 0) * PADW + r0 + 1];
        float hp11 = hs[(nBase + c0 + 1) * PADW + r0 + 1];
        float hp12 = hs[(nBase + c0 + 2) * PADW + r0 + 1];
        float hp13 = hs[(nBase + c0 + 3) * PADW + r0 + 1];

        float4 o0, o1;
        o0.x = hp00 * (1.0f - ALPHA_C) + ALPHA_C * tanhf(xp0.x + p00.x);
        o0.y = hp01 * (1.0f - ALPHA_C) + ALPHA_C * tanhf(xp0.y + p00.y);
        o0.z = hp02 * (1.0f - ALPHA_C) + ALPHA_C * tanhf(xp0.z + p01.x);
        o0.w = hp03 * (1.0f - ALPHA_C) + ALPHA_C * tanhf(xp0.w + p01.y);
        o1.x = hp10 * (1.0f - ALPHA_C) + ALPHA_C * tanhf(xp1.x + p10.x);
        o1.y = hp11 * (1.0f - ALPHA_C) + ALPHA_C * tanhf(xp1.y + p10.y);
        o1.z = hp12 * (1.0f - ALPHA_C) + ALPHA_C * tanhf(xp1.z + p11.x);
        o1.w = hp13 * (1.0f - ALPHA_C) + ALPHA_C * tanhf(xp1.w + p11.y);

        *(float4*)dst = o0;
        *(float4*)(dst + NN) = o1;

        if (t == TT - 1) {  // final hidden state appended after the sequence
            float* tail = out + (size_t)TT * BN + (size_t)(bBase + r0) * NN + nBase + c0;
            *(float4*)tail = o0;
            *(float4*)(tail + NN) = o1;
        }

        // --- group barrier (16 CTAs), monotonic target
        __threadfence();
        __syncthreads();
        if (tid == 0) {
            atomicAdd(&g_bar[bg], 1u);
            const unsigned target = 16u * (unsigned)(t + 1);
            while (*(volatile unsigned*)&g_bar[bg] < target) { }
            __threadfence();
        }
        __syncthreads();
    }
}

extern "C" void kernel_launch(void* const* d_in, const int* in_sizes, int n_in,
                              void* d_out, int out_size)
{
    (void)in_sizes; (void)n_in; (void)out_size;
    const float* x   = (const float*)d_in[0];   // [1000, 256, 128]
    const float* h0  = (const float*)d_in[1];   // [256, 512]
    const float* Win = (const float*)d_in[2];   // [512, 128]
    const float* bin = (const float*)d_in[3];   // [512]
    const float* Whh = (const float*)d_in[4];   // [512, 512]
    float* out = (float*)d_out;                 // [1000*256*512 + 256*512]

    static int smem_set = 0;
    if (!smem_set) {
        cudaFuncSetAttribute(rnn_persistent,
                             cudaFuncAttributeMaxDynamicSharedMemorySize, SMEM_BYTES);
        smem_set = 1;
    }

    // Phase 1: xproj for all timesteps -> out[t] slots (also resets g_bar).
    dim3 gA(NN / 64, (TT * BB) / 64);           // (8, 4000)
    xproj_kernel<<<gA, 256>>>(x, Win, bin, out);

    // Phase 2: persistent recurrence, 128 co-resident CTAs.
    rnn_persistent<<<GROUPS * SLICES, 128, SMEM_BYTES>>>(h0, Whh, out);
}

// round 5
// speedup vs baseline: 1.5961x; 1.5961x over previous
#include <cuda_runtime.h>
#include <math.h>

#define TT 1000
#define BB 256
#define II 128
#define NN 512
#define BN (BB * NN)
#define ALPHA_C 0.2f

#define GROUPS 8      // batch groups of 32 rows
#define SLICES 16     // N slices of 32 cols

#define S_HS 516      // hs row stride (floats): 512 + 4 (stride%32==4 -> conflict-free LDS.128)
#define S_WS 36       // ws row stride (floats): 32 cols + 4 pad (16B multiple)
#define SMEM_BYTES ((32 * S_HS + 512 * S_WS) * 4)

// Per-group monotonic arrival counters; reset by xproj kernel each replay.
__device__ unsigned int g_bar[GROUPS];

typedef unsigned long long u64;

__device__ __forceinline__ u64 pk2(float x, float y) {
    u64 r; asm("mov.b64 %0, {%1, %2};" : "=l"(r) : "f"(x), "f"(y)); return r;
}
__device__ __forceinline__ float2 upk(u64 v) {
    float2 f; asm("mov.b64 {%0, %1}, %2;" : "=f"(f.x), "=f"(f.y) : "l"(v)); return f;
}
__device__ __forceinline__ u64 fma2(u64 a, u64 b, u64 c) {
    u64 r; asm("fma.rn.f32x2 %0, %1, %2, %3;" : "=l"(r) : "l"(a), "l"(b), "l"(c)); return r;
}
__device__ __forceinline__ u64 add2(u64 a, u64 b) {
    u64 r; asm("add.rn.f32x2 %0, %1, %2;" : "=l"(r) : "l"(a), "l"(b)); return r;
}

// ---------------------------------------------------------------------------
// Kernel A: xproj[m, n] = sum_i x[m, i] * W_in[n, i] + b_in[n]
// Written straight into out[t] slots. Packed f32x2 FMA. Also resets g_bar.
// ---------------------------------------------------------------------------
__global__ __launch_bounds__(256) void xproj_kernel(
    const float* __restrict__ X, const float* __restrict__ Win,
    const float* __restrict__ bin, float* __restrict__ C)
{
    if (blockIdx.x == 0 && blockIdx.y == 0 && threadIdx.x < GROUPS)
        g_bar[threadIdx.x] = 0;

    __shared__ float As[16 * 64];
    __shared__ float Bs[16 * 64];

    const int mBase = blockIdx.y * 64;
    const int nBase = blockIdx.x * 64;
    const int tid = threadIdx.x;
    const int lrow = tid >> 2;           // 0..63
    const int lcol = (tid & 3) << 2;     // 0,4,8,12
    const float* Ap = X + (size_t)(mBase + lrow) * II + lcol;
    const float* Bp = Win + (size_t)(nBase + lrow) * II + lcol;

    const int trow = (tid >> 4) << 2;    // m offset within tile
    const int tcol = (tid & 15) << 2;    // n offset within tile

    u64 acc[4][2];
    #pragma unroll
    for (int i = 0; i < 4; i++) { acc[i][0] = 0; acc[i][1] = 0; }

    for (int k0 = 0; k0 < II; k0 += 16) {
        float4 a4 = *(const float4*)(Ap + k0);
        float4 b4 = *(const float4*)(Bp + k0);
        As[(lcol + 0) * 64 + lrow] = a4.x;
        As[(lcol + 1) * 64 + lrow] = a4.y;
        As[(lcol + 2) * 64 + lrow] = a4.z;
        As[(lcol + 3) * 64 + lrow] = a4.w;
        Bs[(lcol + 0) * 64 + lrow] = b4.x;
        Bs[(lcol + 1) * 64 + lrow] = b4.y;
        Bs[(lcol + 2) * 64 + lrow] = b4.z;
        Bs[(lcol + 3) * 64 + lrow] = b4.w;
        __syncthreads();
        #pragma unroll
        for (int kk = 0; kk < 16; kk++) {
            float4 ra4 = *(const float4*)&As[kk * 64 + trow];
            ulonglong2 rb = *(const ulonglong2*)&Bs[kk * 64 + tcol];
            float ra[4] = {ra4.x, ra4.y, ra4.z, ra4.w};
            #pragma unroll
            for (int i = 0; i < 4; i++) {
                u64 d = pk2(ra[i], ra[i]);
                acc[i][0] = fma2(d, rb.x, acc[i][0]);
                acc[i][1] = fma2(d, rb.y, acc[i][1]);
            }
        }
        __syncthreads();
    }

    float4 bv = *(const float4*)&bin[nBase + tcol];
    #pragma unroll
    for (int i = 0; i < 4; i++) {
        float2 p0 = upk(acc[i][0]);
        float2 p1 = upk(acc[i][1]);
        float4 o;
        o.x = p0.x + bv.x;
        o.y = p0.y + bv.y;
        o.z = p1.x + bv.z;
        o.w = p1.y + bv.w;
        *(float4*)&C[(size_t)(mBase + trow + i) * NN + nBase + tcol] = o;
    }
}

// ---------------------------------------------------------------------------
// Persistent recurrence kernel. 128 CTAs = 8 batch-groups x 16 N-slices.
// CTA tile: 32 batch rows x 32 N cols, 256 threads (8 warps, 2/SMSP).
//   hs[32][S_HS]: h_{t-1} rows, ROW-MAJOR (k contiguous) -> per-lane LDS.128 over k
//   ws[512][S_WS]: W_hh slice [k][col] -> per-k uniform (broadcast) LDS.128
// Warp w owns cols w*4..w*4+3, lane = batch row. Thread tile 1x4.
// 4 independent f32x2 accumulator chains (k parity x col pair).
// ---------------------------------------------------------------------------
__global__ __launch_bounds__(256) void rnn_persistent(
    const float* __restrict__ h0, const float* __restrict__ Whh,
    float* __restrict__ out)
{
    extern __shared__ float sm[];
    float* hs = sm;                 // [32][S_HS]
    float* ws = sm + 32 * S_HS;     // [512][S_WS]

    const int cta = blockIdx.x;
    const int bg = cta >> 4;            // batch group 0..7
    const int ns = cta & 15;            // N slice 0..15
    const int bBase = bg * 32;
    const int nBase = ns * 32;
    const int tid = threadIdx.x;        // 0..255
    const int wid = tid >> 5;           // warp 0..7
    const int lane = tid & 31;          // = batch row within tile
    const int c0 = wid * 4;             // warp's 4 columns within slice

    // --- one-time W_hh slice load: ws[k][c] = Whh[(nBase+c)*512 + k]
    for (int idx = tid; idx < 32 * 512; idx += 256) {
        int c = idx >> 9;
        int k = idx & 511;
        ws[k * S_WS + c] = Whh[(size_t)(nBase + c) * NN + k];
    }
    __syncthreads();

    // staging mapping: 8 threads per row, float4 chunks
    const int srow = tid >> 3;          // 0..31
    const int sf4 = tid & 7;            // 0..7

    for (int t = 0; t < TT; t++) {
        // --- stage h_{t-1} rows (row-major), L2 loads (peer-written data)
        const float* src = (t == 0) ? (h0 + (size_t)bBase * NN)
                                    : (out + (size_t)(t - 1) * BN + (size_t)bBase * NN);
        {
            const float4* s4 = (const float4*)(src + (size_t)srow * NN) + sf4;
            float4* d4 = (float4*)(hs + srow * S_HS) + sf4;
            #pragma unroll
            for (int j = 0; j < 16; j++)
                d4[j * 8] = __ldcg(s4 + j * 8);
        }
        __syncthreads();

        // --- GEMM: out cols (nBase+c0..c0+3) for row=lane, K=512
        u64 a0 = 0, a1 = 0, a2 = 0, a3 = 0;   // (even k: cols01, cols23), (odd k: ...)
        const float* hrow = hs + lane * S_HS;
        #pragma unroll 4
        for (int k4 = 0; k4 < 512; k4 += 4) {
            float4 av = *(const float4*)(hrow + k4);
            ulonglong2 b0 = *(const ulonglong2*)&ws[(k4 + 0) * S_WS + c0];
            ulonglong2 b1 = *(const ulonglong2*)&ws[(k4 + 1) * S_WS + c0];
            ulonglong2 b2 = *(const ulonglong2*)&ws[(k4 + 2) * S_WS + c0];
            ulonglong2 b3 = *(const ulonglong2*)&ws[(k4 + 3) * S_WS + c0];
            u64 d0 = pk2(av.x, av.x);
            u64 d1 = pk2(av.y, av.y);
            u64 d2 = pk2(av.z, av.z);
            u64 d3 = pk2(av.w, av.w);
            a0 = fma2(d0, b0.x, a0);
            a1 = fma2(d0, b0.y, a1);
            a2 = fma2(d1, b1.x, a2);
            a3 = fma2(d1, b1.y, a3);
            a0 = fma2(d2, b2.x, a0);
            a1 = fma2(d2, b2.y, a1);
            a2 = fma2(d3, b3.x, a2);
            a3 = fma2(d3, b3.y, a3);
        }
        u64 s01 = add2(a0, a2);             // cols c0, c0+1
        u64 s23 = add2(a1, a3);             // cols c0+2, c0+3
        float2 p01 = upk(s01);
        float2 p23 = upk(s23);

        // --- epilogue: h = 0.8*hprev + 0.2*tanh(xp + acc)
        float* dst = out + (size_t)t * BN + (size_t)(bBase + lane) * NN + nBase + c0;
        float4 xp = *(const float4*)dst;    // xproj value (never in stale L1)
        float4 hp = *(const float4*)(hrow + nBase + c0);

        float4 o;
        o.x = hp.x * (1.0f - ALPHA_C) + ALPHA_C * tanhf(xp.x + p01.x);
        o.y = hp.y * (1.0f - ALPHA_C) + ALPHA_C * tanhf(xp.y + p01.y);
        o.z = hp.z * (1.0f - ALPHA_C) + ALPHA_C * tanhf(xp.z + p23.x);
        o.w = hp.w * (1.0f - ALPHA_C) + ALPHA_C * tanhf(xp.w + p23.y);

        __stcg((float4*)dst, o);
        if (t == TT - 1) {  // final hidden state appended after the sequence
            float* tail = out + (size_t)TT * BN + (size_t)(bBase + lane) * NN + nBase + c0;
            __stcg((float4*)tail, o);
        }

        // --- group barrier (16 CTAs sharing these batch rows), monotonic
        __threadfence();
        __syncthreads();
        if (tid == 0) {
            atomicAdd(&g_bar[bg], 1u);
            const unsigned target = 16u * (unsigned)(t + 1);
            while (*(volatile unsigned*)&g_bar[bg] < target) { __nanosleep(40); }
            __threadfence();
        }
        __syncthreads();
    }
}

extern "C" void kernel_launch(void* const* d_in, const int* in_sizes, int n_in,
                              void* d_out, int out_size)
{
    (void)in_sizes; (void)n_in; (void)out_size;
    const float* x   = (const float*)d_in[0];   // [1000, 256, 128]
    const float* h0  = (const float*)d_in[1];   // [256, 512]
    const float* Win = (const float*)d_in[2];   // [512, 128]
    const float* bin = (const float*)d_in[3];   // [512]
    const float* Whh = (const float*)d_in[4];   // [512, 512]
    float* out = (float*)d_out;                 // [1000*256*512 + 256*512]

    static int smem_set = 0;
    if (!smem_set) {
        cudaFuncSetAttribute(rnn_persistent,
                             cudaFuncAttributeMaxDynamicSharedMemorySize, SMEM_BYTES);
        smem_set = 1;
    }

    // Phase 1: xproj for all timesteps -> out[t] slots (also resets g_bar).
    dim3 gA(NN / 64, (TT * BB) / 64);           // (8, 4000)
    xproj_kernel<<<gA, 256>>>(x, Win, bin, out);

    // Phase 2: persistent recurrence, 128 co-resident CTAs.
    rnn_persistent<<<GROUPS * SLICES, 256, SMEM_BYTES>>>(h0, Whh, out);
}

// round 10
// speedup vs baseline: 1.7758x; 1.1126x over previous
#include <cuda_runtime.h>
#include <math.h>

#define TT 1000
#define BB 256
#define II 128
#define NN 512
#define BN (BB * NN)
#define ALPHA_C 0.2f

#define GROUPS 8      // batch groups of 32 rows
#define SLICES 16     // N slices of 32 cols

#define S_HS 36       // hs row stride in floats (32 rows + 4 pad; 144B, 16B-aligned)
#define HS_FLOATS (512 * S_HS)                 // 18432 floats = 73728 B
#define RED_BYTES (8 * 16 * 32 * 8)            // 8 warps x 16 row-pairs x 32 cols x u64
#define SMEM_BYTES (HS_FLOATS * 4 + RED_BYTES) // 106496 B

// Per-group monotonic arrival counters; reset by xproj kernel each replay.
__device__ unsigned int g_bar[GROUPS];

typedef unsigned long long u64;

__device__ __forceinline__ u64 pk2(float x, float y) {
    u64 r; asm("mov.b64 %0, {%1, %2};" : "=l"(r) : "f"(x), "f"(y)); return r;
}
__device__ __forceinline__ float2 upk(u64 v) {
    float2 f; asm("mov.b64 {%0, %1}, %2;" : "=f"(f.x), "=f"(f.y) : "l"(v)); return f;
}
__device__ __forceinline__ u64 fma2(u64 a, u64 b, u64 c) {
    u64 r; asm("fma.rn.f32x2 %0, %1, %2, %3;" : "=l"(r) : "l"(a), "l"(b), "l"(c)); return r;
}
__device__ __forceinline__ u64 add2(u64 a, u64 b) {
    u64 r; asm("add.rn.f32x2 %0, %1, %2;" : "=l"(r) : "l"(a), "l"(b)); return r;
}

// ---------------------------------------------------------------------------
// Kernel A: xproj[m, n] = sum_i x[m, i] * W_in[n, i] + b_in[n]
// Written straight into out[t] slots. Packed f32x2 FMA. Also resets g_bar.
// ---------------------------------------------------------------------------
__global__ __launch_bounds__(256) void xproj_kernel(
    const float* __restrict__ X, const float* __restrict__ Win,
    const float* __restrict__ bin, float* __restrict__ C)
{
    if (blockIdx.x == 0 && blockIdx.y == 0 && threadIdx.x < GROUPS)
        g_bar[threadIdx.x] = 0;

    __shared__ float As[16 * 64];
    __shared__ float Bs[16 * 64];

    const int mBase = blockIdx.y * 64;
    const int nBase = blockIdx.x * 64;
    const int tid = threadIdx.x;
    const int lrow = tid >> 2;           // 0..63
    const int lcol = (tid & 3) << 2;     // 0,4,8,12
    const float* Ap = X + (size_t)(mBase + lrow) * II + lcol;
    const float* Bp = Win + (size_t)(nBase + lrow) * II + lcol;

    const int trow = (tid >> 4) << 2;    // m offset within tile
    const int tcol = (tid & 15) << 2;    // n offset within tile

    u64 acc[4][2];
    #pragma unroll
    for (int i = 0; i < 4; i++) { acc[i][0] = 0; acc[i][1] = 0; }

    for (int k0 = 0; k0 < II; k0 += 16) {
        float4 a4 = *(const float4*)(Ap + k0);
        float4 b4 = *(const float4*)(Bp + k0);
        As[(lcol + 0) * 64 + lrow] = a4.x;
        As[(lcol + 1) * 64 + lrow] = a4.y;
        As[(lcol + 2) * 64 + lrow] = a4.z;
        As[(lcol + 3) * 64 + lrow] = a4.w;
        Bs[(lcol + 0) * 64 + lrow] = b4.x;
        Bs[(lcol + 1) * 64 + lrow] = b4.y;
        Bs[(lcol + 2) * 64 + lrow] = b4.z;
        Bs[(lcol + 3) * 64 + lrow] = b4.w;
        __syncthreads();
        #pragma unroll
        for (int kk = 0; kk < 16; kk++) {
            float4 ra4 = *(const float4*)&As[kk * 64 + trow];
            ulonglong2 rb = *(const ulonglong2*)&Bs[kk * 64 + tcol];
            float ra[4] = {ra4.x, ra4.y, ra4.z, ra4.w};
            #pragma unroll
            for (int i = 0; i < 4; i++) {
                u64 d = pk2(ra[i], ra[i]);
                acc[i][0] = fma2(d, rb.x, acc[i][0]);
                acc[i][1] = fma2(d, rb.y, acc[i][1]);
            }
        }
        __syncthreads();
    }

    float4 bv = *(const float4*)&bin[nBase + tcol];
    #pragma unroll
    for (int i = 0; i < 4; i++) {
        float2 p0 = upk(acc[i][0]);
        float2 p1 = upk(acc[i][1]);
        float4 o;
        o.x = p0.x + bv.x;
        o.y = p0.y + bv.y;
        o.z = p1.x + bv.z;
        o.w = p1.y + bv.w;
        *(float4*)&C[(size_t)(mBase + trow + i) * NN + nBase + tcol] = o;
    }
}

// ---------------------------------------------------------------------------
// Persistent recurrence kernel. 128 CTAs = 8 batch-groups x 16 N-slices.
// CTA tile: 32 batch rows x 32 N cols, 256 threads (8 warps).
//   - Warp w: lane = column, K-chunk [w*64, w*64+64). W values in REGISTERS
//     (64 per lane, loaded once for all 1000 steps) -> zero W smem traffic.
//   - hs[k][b] (transposed, stride 36): per k, 8 broadcast LDS.128 deliver all
//     32 rows as packed f32x2 row-pairs -> each h element read once per CTA.
//   - Staging: row-grouped coalesced loads (warp covers 4 rows x 128B chunks,
//     4 lines/LDG) -> transpose via STS.32 (4-way bank conflicts, acceptable).
//   - 16 packed accumulators (row-pairs) per thread; cross-warp K reduction
//     through a smem partial buffer with add.rn.f32x2.
// ---------------------------------------------------------------------------
__global__ __launch_bounds__(256, 1) void rnn_persistent(
    const float* __restrict__ h0, const float* __restrict__ Whh,
    float* __restrict__ out)
{
    extern __shared__ float sm[];
    float* hs = sm;                         // [512][S_HS]
    u64* red = (u64*)(sm + HS_FLOATS);      // [8 warps][16 pairs][32 cols]

    const int cta = blockIdx.x;
    const int bg = cta >> 4;            // batch group 0..7
    const int ns = cta & 15;            // N slice 0..15
    const int bBase = bg * 32;
    const int nBase = ns * 32;
    const int tid = threadIdx.x;        // 0..255
    const int wid = tid >> 5;           // warp 0..7 -> K-chunk
    const int lane = tid & 31;          // = column within slice

    // --- one-time W load into registers: Wreg[j] = Whh[(nBase+lane)*512 + wid*64 + j]
    float Wreg[64];
    {
        const float* wp = Whh + (size_t)(nBase + lane) * NN + wid * 64;
        #pragma unroll
        for (int j = 0; j < 16; j++) {
            float4 v = __ldg((const float4*)(wp + j * 4));
            Wreg[j * 4 + 0] = v.x;
            Wreg[j * 4 + 1] = v.y;
            Wreg[j * 4 + 2] = v.z;
            Wreg[j * 4 + 3] = v.w;
        }
    }

    // staging mapping: warp covers 4 rows, 8 lanes sweep each row's float4s
    const int srow = wid * 4 + (lane >> 3);  // 0..31
    const int sf = lane & 7;                 // float4 phase within row

    // epilogue mapping: row-pair p, two columns c0, c0+1
    const int ep = tid >> 4;            // 0..15
    const int ec0 = (tid & 15) * 2;     // 0,2,..,30

    for (int t = 0; t < TT; t++) {
        // --- stage h_{t-1} (transpose to hs[k][b]), coalesced L2 loads
        {
            const float* src = ((t == 0) ? (h0 + (size_t)bBase * NN)
                                         : (out + (size_t)(t - 1) * BN + (size_t)bBase * NN))
                               + (size_t)srow * NN;
            #pragma unroll 4
            for (int j = 0; j < 16; j++) {
                const int kb = (j * 8 + sf) * 4;
                float4 v = __ldcg((const float4*)(src + kb));
                hs[(kb + 0) * S_HS + srow] = v.x;
                hs[(kb + 1) * S_HS + srow] = v.y;
                hs[(kb + 2) * S_HS + srow] = v.z;
                hs[(kb + 3) * S_HS + srow] = v.w;
            }
        }
        __syncthreads();

        // --- GEMM partial over this warp's K-chunk; acc[p] = rows (2p, 2p+1)
        u64 acc[16];
        #pragma unroll
        for (int p = 0; p < 16; p++) acc[p] = 0;

        const float* hk = hs + wid * 64 * S_HS;
        #pragma unroll 16
        for (int kk = 0; kk < 64; kk++) {
            const float* hrow = hk + kk * S_HS;
            u64 wsp = pk2(Wreg[kk], Wreg[kk]);
            #pragma unroll
            for (int q = 0; q < 8; q++) {
                ulonglong2 h2 = *(const ulonglong2*)(hrow + q * 4);  // rows 4q..4q+3
                acc[2 * q + 0] = fma2(h2.x, wsp, acc[2 * q + 0]);
                acc[2 * q + 1] = fma2(h2.y, wsp, acc[2 * q + 1]);
            }
        }

        // --- write partials: red[wid][p][lane]
        #pragma unroll
        for (int p = 0; p < 16; p++)
            red[(wid * 16 + p) * 32 + lane] = acc[p];
        __syncthreads();

        // --- reduce 8 warps + epilogue for (rows 2ep,2ep+1) x (cols ec0,ec0+1)
        u64 s0 = red[(0 * 16 + ep) * 32 + ec0];
        u64 s1 = red[(0 * 16 + ep) * 32 + ec0 + 1];
        #pragma unroll
        for (int w = 1; w < 8; w++) {
            s0 = add2(s0, red[(w * 16 + ep) * 32 + ec0]);
            s1 = add2(s1, red[(w * 16 + ep) * 32 + ec0 + 1]);
        }
        float2 r0 = upk(s0);   // col ec0:   rows 2ep, 2ep+1
        float2 r1 = upk(s1);   // col ec0+1: rows 2ep, 2ep+1

        const int b0 = 2 * ep;
        float* dst0 = out + (size_t)t * BN + (size_t)(bBase + b0) * NN + nBase + ec0;
        float* dst1 = dst0 + NN;
        float2 xp0 = *(const float2*)dst0;   // row b0:  cols ec0, ec0+1
        float2 xp1 = *(const float2*)dst1;   // row b0+1

        float hp00 = hs[(nBase + ec0) * S_HS + b0];
        float hp01 = hs[(nBase + ec0 + 1) * S_HS + b0];
        float hp10 = hs[(nBase + ec0) * S_HS + b0 + 1];
        float hp11 = hs[(nBase + ec0 + 1) * S_HS + b0 + 1];

        float2 o0, o1;
        o0.x = hp00 * (1.0f - ALPHA_C) + ALPHA_C * tanhf(xp0.x + r0.x);
        o0.y = hp01 * (1.0f - ALPHA_C) + ALPHA_C * tanhf(xp0.y + r1.x);
        o1.x = hp10 * (1.0f - ALPHA_C) + ALPHA_C * tanhf(xp1.x + r0.y);
        o1.y = hp11 * (1.0f - ALPHA_C) + ALPHA_C * tanhf(xp1.y + r1.y);

        __stcg((float2*)dst0, o0);
        __stcg((float2*)dst1, o1);
        if (t == TT - 1) {  // final hidden state appended after the sequence
            float* tail = out + (size_t)TT * BN + (size_t)(bBase + b0) * NN + nBase + ec0;
            __stcg((float2*)tail, o0);
            __stcg((float2*)(tail + NN), o1);
        }

        // --- group barrier (16 CTAs sharing these batch rows), monotonic
        __threadfence();
        __syncthreads();
        if (tid == 0) {
            atomicAdd(&g_bar[bg], 1u);
            const unsigned target = 16u * (unsigned)(t + 1);
            while (*(volatile unsigned*)&g_bar[bg] < target) { __nanosleep(40); }
            __threadfence();
        }
        __syncthreads();
    }
}

extern "C" void kernel_launch(void* const* d_in, const int* in_sizes, int n_in,
                              void* d_out, int out_size)
{
    (void)in_sizes; (void)n_in; (void)out_size;
    const float* x   = (const float*)d_in[0];   // [1000, 256, 128]
    const float* h0  = (const float*)d_in[1];   // [256, 512]
    const float* Win = (const float*)d_in[2];   // [512, 128]
    const float* bin = (const float*)d_in[3];   // [512]
    const float* Whh = (const float*)d_in[4];   // [512, 512]
    float* out = (float*)d_out;                 // [1000*256*512 + 256*512]

    static int smem_set = 0;
    if (!smem_set) {
        cudaFuncSetAttribute(rnn_persistent,
                             cudaFuncAttributeMaxDynamicSharedMemorySize, SMEM_BYTES);
        smem_set = 1;
    }

    // Phase 1: xproj for all timesteps -> out[t] slots (also resets g_bar).
    dim3 gA(NN / 64, (TT * BB) / 64);           // (8, 4000)
    xproj_kernel<<<gA, 256>>>(x, Win, bin, out);

    // Phase 2: persistent recurrence, 128 co-resident CTAs.
    rnn_persistent<<<GROUPS * SLICES, 256, SMEM_BYTES>>>(h0, Whh, out);
}

// round 12
// speedup vs baseline: 2.0377x; 1.1475x over previous
#include <cuda_runtime.h>
#include <math.h>

#define TT 1000
#define BB 256
#define II 128
#define NN 512
#define BN (BB * NN)
#define ALPHA_C 0.2f

#define GROUPS 8      // batch groups of 32 rows
#define SLICES 16     // N slices of 32 cols

#define S_HS 516      // hs row stride (floats): 512 + 4; 2064B = 16B multiple
#define HS_FLOATS (32 * S_HS)                  // 16512 floats = 66048 B
#define RED_FLOATS (16 * 32 * 32)              // 16 K-chunks x 32 rows x 32 cols
#define SMEM_BYTES ((HS_FLOATS + RED_FLOATS) * 4)   // 131584 B

// Per-group monotonic arrival counters; reset by xproj kernel each replay.
__device__ unsigned int g_bar[GROUPS];

typedef unsigned long long u64;

__device__ __forceinline__ u64 pk2(float x, float y) {
    u64 r; asm("mov.b64 %0, {%1, %2};" : "=l"(r) : "f"(x), "f"(y)); return r;
}
__device__ __forceinline__ float2 upk(u64 v) {
    float2 f; asm("mov.b64 {%0, %1}, %2;" : "=f"(f.x), "=f"(f.y) : "l"(v)); return f;
}
__device__ __forceinline__ u64 fma2(u64 a, u64 b, u64 c) {
    u64 r; asm("fma.rn.f32x2 %0, %1, %2, %3;" : "=l"(r) : "l"(a), "l"(b), "l"(c)); return r;
}
__device__ __forceinline__ u64 add2(u64 a, u64 b) {
    u64 r; asm("add.rn.f32x2 %0, %1, %2;" : "=l"(r) : "l"(a), "l"(b)); return r;
}

// ---------------------------------------------------------------------------
// Kernel A: xproj[m, n] = sum_i x[m, i] * W_in[n, i] + b_in[n]
// Written straight into out[t] slots. Packed f32x2 FMA. Also resets g_bar.
// ---------------------------------------------------------------------------
__global__ __launch_bounds__(256) void xproj_kernel(
    const float* __restrict__ X, const float* __restrict__ Win,
    const float* __restrict__ bin, float* __restrict__ C)
{
    if (blockIdx.x == 0 && blockIdx.y == 0 && threadIdx.x < GROUPS)
        g_bar[threadIdx.x] = 0;

    __shared__ float As[16 * 64];
    __shared__ float Bs[16 * 64];

    const int mBase = blockIdx.y * 64;
    const int nBase = blockIdx.x * 64;
    const int tid = threadIdx.x;
    const int lrow = tid >> 2;           // 0..63
    const int lcol = (tid & 3) << 2;     // 0,4,8,12
    const float* Ap = X + (size_t)(mBase + lrow) * II + lcol;
    const float* Bp = Win + (size_t)(nBase + lrow) * II + lcol;

    const int trow = (tid >> 4) << 2;    // m offset within tile
    const int tcol = (tid & 15) << 2;    // n offset within tile

    u64 acc[4][2];
    #pragma unroll
    for (int i = 0; i < 4; i++) { acc[i][0] = 0; acc[i][1] = 0; }

    for (int k0 = 0; k0 < II; k0 += 16) {
        float4 a4 = *(const float4*)(Ap + k0);
        float4 b4 = *(const float4*)(Bp + k0);
        As[(lcol + 0) * 64 + lrow] = a4.x;
        As[(lcol + 1) * 64 + lrow] = a4.y;
        As[(lcol + 2) * 64 + lrow] = a4.z;
        As[(lcol + 3) * 64 + lrow] = a4.w;
        Bs[(lcol + 0) * 64 + lrow] = b4.x;
        Bs[(lcol + 1) * 64 + lrow] = b4.y;
        Bs[(lcol + 2) * 64 + lrow] = b4.z;
        Bs[(lcol + 3) * 64 + lrow] = b4.w;
        __syncthreads();
        #pragma unroll
        for (int kk = 0; kk < 16; kk++) {
            float4 ra4 = *(const float4*)&As[kk * 64 + trow];
            ulonglong2 rb = *(const ulonglong2*)&Bs[kk * 64 + tcol];
            float ra[4] = {ra4.x, ra4.y, ra4.z, ra4.w};
            #pragma unroll
            for (int i = 0; i < 4; i++) {
                u64 d = pk2(ra[i], ra[i]);
                acc[i][0] = fma2(d, rb.x, acc[i][0]);
                acc[i][1] = fma2(d, rb.y, acc[i][1]);
            }
        }
        __syncthreads();
    }

    float4 bv = *(const float4*)&bin[nBase + tcol];
    #pragma unroll
    for (int i = 0; i < 4; i++) {
        float2 p0 = upk(acc[i][0]);
        float2 p1 = upk(acc[i][1]);
        float4 o;
        o.x = p0.x + bv.x;
        o.y = p0.y + bv.y;
        o.z = p1.x + bv.z;
        o.w = p1.y + bv.w;
        *(float4*)&C[(size_t)(mBase + trow + i) * NN + nBase + tcol] = o;
    }
}

// ---------------------------------------------------------------------------
// Persistent recurrence kernel. 128 CTAs = 8 batch-groups x 16 N-slices.
// CTA tile: 32 batch rows x 32 N cols, 512 threads (16 warps, 4/SMSP).
//   - hs[32][516] ROW-major: staging = coalesced LDG.128 + conflict-free
//     STS.128, no transpose.
//   - Warp w: K-chunk [32w, 32w+32), lane = column. W held as 16 packed-u64
//     (k-pairs) registers per lane, loaded once for all 1000 steps.
//   - GEMM inner loop over rows: 1 broadcast LDS.128 (ulonglong2, register-
//     pair aliased) + 2 FMA2 per (row, 4k). Rows in 2 passes of 16 to cap
//     registers; 16 independent acc chains per pass.
//   - K reduction across 16 warps via scalar red[16][32][32] smem buffer.
// ---------------------------------------------------------------------------
__global__ __launch_bounds__(512, 1) void rnn_persistent(
    const float* __restrict__ h0, const float* __restrict__ Whh,
    float* __restrict__ out)
{
    extern __shared__ float sm[];
    float* hs = sm;                         // [32][S_HS]
    float* red = sm + HS_FLOATS;            // [16][32][32]

    const int cta = blockIdx.x;
    const int bg = cta >> 4;            // batch group 0..7
    const int ns = cta & 15;            // N slice 0..15
    const int bBase = bg * 32;
    const int nBase = ns * 32;
    const int tid = threadIdx.x;        // 0..511
    const int wid = tid >> 5;           // warp 0..15 -> K-chunk
    const int lane = tid & 31;          // = column within slice

    // --- one-time W load: Wp[j] = (W[nBase+lane][32w+2j], [..2j+1]) packed
    u64 Wp[16];
    {
        const float* wp = Whh + (size_t)(nBase + lane) * NN + wid * 32;
        #pragma unroll
        for (int i = 0; i < 8; i++) {
            ulonglong2 v = __ldg((const ulonglong2*)(wp + i * 4));
            Wp[2 * i + 0] = v.x;
            Wp[2 * i + 1] = v.y;
        }
    }

    // staging mapping: srow = tid>>4 (0..31), sf = tid&15 (float4 phase)
    const int srow = tid >> 4;
    const int sf = tid & 15;

    // reduce/epilogue mapping: row r, col pair (c0, c0+1)
    const int er = tid >> 4;            // 0..31
    const int ec0 = (tid & 15) * 2;     // 0,2,..,30

    for (int t = 0; t < TT; t++) {
        // --- stage h_{t-1} rows (row-major), coalesced, conflict-free
        {
            const float* src = ((t == 0) ? (h0 + (size_t)bBase * NN)
                                         : (out + (size_t)(t - 1) * BN + (size_t)bBase * NN))
                               + (size_t)srow * NN;
            float* dstr = hs + srow * S_HS;
            #pragma unroll
            for (int j = 0; j < 8; j++) {
                const int kb = (j * 16 + sf) * 4;
                float4 v = __ldcg((const float4*)(src + kb));
                *(float4*)(dstr + kb) = v;
            }
        }
        __syncthreads();

        // --- GEMM over this warp's K-chunk, rows in 2 passes of 16
        const float* hbase = hs + wid * 32;     // k-offset within each row
        #pragma unroll
        for (int pass = 0; pass < 2; pass++) {
            u64 acc[16];
            #pragma unroll
            for (int r = 0; r < 16; r++) acc[r] = 0;

            #pragma unroll
            for (int j = 0; j < 8; j++) {           // 4 k's per j
                #pragma unroll
                for (int r = 0; r < 16; r++) {
                    ulonglong2 hv = *(const ulonglong2*)(hbase + (pass * 16 + r) * S_HS + 4 * j);
                    acc[r] = fma2(hv.x, Wp[2 * j + 0], acc[r]);
                    acc[r] = fma2(hv.y, Wp[2 * j + 1], acc[r]);
                }
            }

            // horizontal add + write partials: red[wid][row][lane]
            #pragma unroll
            for (int r = 0; r < 16; r++) {
                float2 p = upk(acc[r]);
                red[(wid * 32 + pass * 16 + r) * 32 + lane] = p.x + p.y;
            }
        }
        __syncthreads();

        // --- reduce 16 K-chunks + epilogue for row er, cols (ec0, ec0+1)
        u64 s = *(const u64*)&red[(0 * 32 + er) * 32 + ec0];
        #pragma unroll
        for (int w = 1; w < 16; w++)
            s = add2(s, *(const u64*)&red[(w * 32 + er) * 32 + ec0]);
        float2 p = upk(s);      // (col ec0, col ec0+1)

        float* dst = out + (size_t)t * BN + (size_t)(bBase + er) * NN + nBase + ec0;
        float2 xp = *(const float2*)dst;                       // xproj value
        float2 hp = *(const float2*)(hs + er * S_HS + nBase + ec0);  // hprev

        float2 o;
        o.x = hp.x * (1.0f - ALPHA_C) + ALPHA_C * tanhf(xp.x + p.x);
        o.y = hp.y * (1.0f - ALPHA_C) + ALPHA_C * tanhf(xp.y + p.y);

        __stcg((float2*)dst, o);
        if (t == TT - 1) {  // final hidden state appended after the sequence
            float* tail = out + (size_t)TT * BN + (size_t)(bBase + er) * NN + nBase + ec0;
            __stcg((float2*)tail, o);
        }

        // --- group barrier (16 CTAs sharing these batch rows), monotonic
        __threadfence();
        __syncthreads();
        if (t < TT - 1) {
            if (tid == 0) {
                atomicAdd(&g_bar[bg], 1u);
                const unsigned target = 16u * (unsigned)(t + 1);
                while (*(volatile unsigned*)&g_bar[bg] < target) { __nanosleep(40); }
                __threadfence();
            }
            __syncthreads();
        }
    }
}

extern "C" void kernel_launch(void* const* d_in, const int* in_sizes, int n_in,
                              void* d_out, int out_size)
{
    (void)in_sizes; (void)n_in; (void)out_size;
    const float* x   = (const float*)d_in[0];   // [1000, 256, 128]
    const float* h0  = (const float*)d_in[1];   // [256, 512]
    const float* Win = (const float*)d_in[2];   // [512, 128]
    const float* bin = (const float*)d_in[3];   // [512]
    const float* Whh = (const float*)d_in[4];   // [512, 512]
    float* out = (float*)d_out;                 // [1000*256*512 + 256*512]

    static int smem_set = 0;
    if (!smem_set) {
        cudaFuncSetAttribute(rnn_persistent,
                             cudaFuncAttributeMaxDynamicSharedMemorySize, SMEM_BYTES);
        smem_set = 1;
    }

    // Phase 1: xproj for all timesteps -> out[t] slots (also resets g_bar).
    dim3 gA(NN / 64, (TT * BB) / 64);           // (8, 4000)
    xproj_kernel<<<gA, 256>>>(x, Win, bin, out);

    // Phase 2: persistent recurrence, 128 co-resident CTAs.
    rnn_persistent<<<GROUPS * SLICES, 512, SMEM_BYTES>>>(h0, Whh, out);
}

// round 13
// speedup vs baseline: 2.2272x; 1.0930x over previous
#include <cuda_runtime.h>
#include <math.h>

#define TT 1000
#define BB 256
#define II 128
#define NN 512
#define BN (BB * NN)
#define ALPHA_C 0.2f

#define GROUPS 8      // batch groups of 32 rows
#define SLICES 16     // N slices of 32 cols

#define S_BUF 36      // per-warp h buffer row stride (floats); rows 16B-aligned
#define BUF_FLOATS (32 * S_BUF)                // 1152 floats per warp
#define HS_FLOATS (16 * BUF_FLOATS)            // 18432 floats = 73728 B
#define RED_FLOATS (16 * 32 * 32)              // 16 K-chunks x 32 rows x 32 cols
#define SMEM_BYTES ((HS_FLOATS + RED_FLOATS) * 4)   // 139264 B

// Per-group monotonic arrival counters; reset by xproj kernel each replay.
__device__ unsigned int g_bar[GROUPS];

typedef unsigned long long u64;

__device__ __forceinline__ u64 pk2(float x, float y) {
    u64 r; asm("mov.b64 %0, {%1, %2};" : "=l"(r) : "f"(x), "f"(y)); return r;
}
__device__ __forceinline__ float2 upk(u64 v) {
    float2 f; asm("mov.b64 {%0, %1}, %2;" : "=f"(f.x), "=f"(f.y) : "l"(v)); return f;
}
__device__ __forceinline__ u64 fma2(u64 a, u64 b, u64 c) {
    u64 r; asm("fma.rn.f32x2 %0, %1, %2, %3;" : "=l"(r) : "l"(a), "l"(b), "l"(c)); return r;
}
__device__ __forceinline__ u64 add2(u64 a, u64 b) {
    u64 r; asm("add.rn.f32x2 %0, %1, %2;" : "=l"(r) : "l"(a), "l"(b)); return r;
}

// ---------------------------------------------------------------------------
// Kernel A: xproj[m, n] = sum_i x[m, i] * W_in[n, i] + b_in[n]
// Written straight into out[t] slots. Packed f32x2 FMA. Also resets g_bar.
// ---------------------------------------------------------------------------
__global__ __launch_bounds__(256) void xproj_kernel(
    const float* __restrict__ X, const float* __restrict__ Win,
    const float* __restrict__ bin, float* __restrict__ C)
{
    if (blockIdx.x == 0 && blockIdx.y == 0 && threadIdx.x < GROUPS)
        g_bar[threadIdx.x] = 0;

    __shared__ float As[16 * 64];
    __shared__ float Bs[16 * 64];

    const int mBase = blockIdx.y * 64;
    const int nBase = blockIdx.x * 64;
    const int tid = threadIdx.x;
    const int lrow = tid >> 2;           // 0..63
    const int lcol = (tid & 3) << 2;     // 0,4,8,12
    const float* Ap = X + (size_t)(mBase + lrow) * II + lcol;
    const float* Bp = Win + (size_t)(nBase + lrow) * II + lcol;

    const int trow = (tid >> 4) << 2;    // m offset within tile
    const int tcol = (tid & 15) << 2;    // n offset within tile

    u64 acc[4][2];
    #pragma unroll
    for (int i = 0; i < 4; i++) { acc[i][0] = 0; acc[i][1] = 0; }

    for (int k0 = 0; k0 < II; k0 += 16) {
        float4 a4 = *(const float4*)(Ap + k0);
        float4 b4 = *(const float4*)(Bp + k0);
        As[(lcol + 0) * 64 + lrow] = a4.x;
        As[(lcol + 1) * 64 + lrow] = a4.y;
        As[(lcol + 2) * 64 + lrow] = a4.z;
        As[(lcol + 3) * 64 + lrow] = a4.w;
        Bs[(lcol + 0) * 64 + lrow] = b4.x;
        Bs[(lcol + 1) * 64 + lrow] = b4.y;
        Bs[(lcol + 2) * 64 + lrow] = b4.z;
        Bs[(lcol + 3) * 64 + lrow] = b4.w;
        __syncthreads();
        #pragma unroll
        for (int kk = 0; kk < 16; kk++) {
            float4 ra4 = *(const float4*)&As[kk * 64 + trow];
            ulonglong2 rb = *(const ulonglong2*)&Bs[kk * 64 + tcol];
            float ra[4] = {ra4.x, ra4.y, ra4.z, ra4.w};
            #pragma unroll
            for (int i = 0; i < 4; i++) {
                u64 d = pk2(ra[i], ra[i]);
                acc[i][0] = fma2(d, rb.x, acc[i][0]);
                acc[i][1] = fma2(d, rb.y, acc[i][1]);
            }
        }
        __syncthreads();
    }

    float4 bv = *(const float4*)&bin[nBase + tcol];
    #pragma unroll
    for (int i = 0; i < 4; i++) {
        float2 p0 = upk(acc[i][0]);
        float2 p1 = upk(acc[i][1]);
        float4 o;
        o.x = p0.x + bv.x;
        o.y = p0.y + bv.y;
        o.z = p1.x + bv.z;
        o.w = p1.y + bv.w;
        *(float4*)&C[(size_t)(mBase + trow + i) * NN + nBase + tcol] = o;
    }
}

// ---------------------------------------------------------------------------
// Persistent recurrence kernel. 128 CTAs = 8 batch-groups x 16 N-slices.
// CTA tile: 32 batch rows x 32 N cols, 512 threads (16 warps, 4/SMSP).
//   - Warp w: K-chunk [32w, 32w+32), lane = column. W as 16 packed-u64 regs.
//   - WARP-PRIVATE staging: warp w loads only its 32-row x 32-k slice of
//     h_{t-1} into its own smem buffer (stride 36) -> __syncwarp, no CTA sync
//     between staging and GEMM.
//   - GEMM inner loop over rows: broadcast LDS.128 + 2 FMA2 per (row, 4k).
//     Rows in 2 passes of 16; 16 independent acc chains per pass.
//   - K reduction across 16 warps via red[16][32][32] smem.
//   - xp prefetched at loop top; barrier = bar + tid0 fence/atomic/acquire.
// ---------------------------------------------------------------------------
__global__ __launch_bounds__(512, 1) void rnn_persistent(
    const float* __restrict__ h0, const float* __restrict__ Whh,
    float* __restrict__ out)
{
    extern __shared__ float sm[];
    float* red = sm + HS_FLOATS;            // [16][32][32]

    const int cta = blockIdx.x;
    const int bg = cta >> 4;            // batch group 0..7
    const int ns = cta & 15;            // N slice 0..15
    const int bBase = bg * 32;
    const int nBase = ns * 32;
    const int tid = threadIdx.x;        // 0..511
    const int wid = tid >> 5;           // warp 0..15 -> K-chunk
    const int lane = tid & 31;          // = column within slice

    float* buf = sm + wid * BUF_FLOATS;     // this warp's h slice [32][S_BUF]

    // --- one-time W load: Wp[2i], Wp[2i+1] = packed k-pairs of W[nBase+lane][32w+4i..]
    u64 Wp[16];
    {
        const float* wp = Whh + (size_t)(nBase + lane) * NN + wid * 32;
        #pragma unroll
        for (int i = 0; i < 8; i++) {
            ulonglong2 v = __ldg((const ulonglong2*)(wp + i * 4));
            Wp[2 * i + 0] = v.x;
            Wp[2 * i + 1] = v.y;
        }
    }

    // staging mapping (within warp): 8 lanes per row, 4 rows per instruction
    const int sa = lane >> 3;           // 0..3 row sub-index
    const int sp = lane & 7;            // float4 phase within the 32-float slice

    // reduce/epilogue mapping: row er, col pair (ec0, ec0+1)
    const int er = tid >> 4;            // 0..31
    const int ec0 = (tid & 15) * 2;     // 0,2,..,30

    for (int t = 0; t < TT; t++) {
        // --- prefetch xproj for epilogue (hidden under staging + GEMM)
        float2 xp = __ldcg((const float2*)(out + (size_t)t * BN
                                           + (size_t)(bBase + er) * NN + nBase + ec0));

        // --- warp-private staging of h_{t-1} k-slice [32 rows][32 k]
        {
            const float* src = ((t == 0) ? (h0 + (size_t)bBase * NN)
                                         : (out + (size_t)(t - 1) * BN + (size_t)bBase * NN))
                               + wid * 32 + sp * 4;
            #pragma unroll
            for (int i = 0; i < 8; i++) {
                const int row = i * 4 + sa;
                float4 v = __ldcg((const float4*)(src + (size_t)row * NN));
                *(float4*)(buf + row * S_BUF + sp * 4) = v;
            }
        }
        __syncwarp();

        // --- GEMM over this warp's K-chunk, rows in 2 passes of 16
        #pragma unroll
        for (int pass = 0; pass < 2; pass++) {
            u64 acc[16];
            #pragma unroll
            for (int r = 0; r < 16; r++) acc[r] = 0;

            #pragma unroll
            for (int j = 0; j < 8; j++) {           // 4 k's per j
                #pragma unroll
                for (int r = 0; r < 16; r++) {
                    ulonglong2 hv = *(const ulonglong2*)(buf + (pass * 16 + r) * S_BUF + 4 * j);
                    acc[r] = fma2(hv.x, Wp[2 * j + 0], acc[r]);
                    acc[r] = fma2(hv.y, Wp[2 * j + 1], acc[r]);
                }
            }

            // horizontal add + write partials: red[wid][row][lane]
            #pragma unroll
            for (int r = 0; r < 16; r++) {
                float2 p = upk(acc[r]);
                red[(wid * 32 + pass * 16 + r) * 32 + lane] = p.x + p.y;
            }
        }
        __syncthreads();

        // --- reduce 16 K-chunks + epilogue for row er, cols (ec0, ec0+1)
        u64 s = *(const u64*)&red[(0 * 32 + er) * 32 + ec0];
        #pragma unroll
        for (int w = 1; w < 16; w++)
            s = add2(s, *(const u64*)&red[(w * 32 + er) * 32 + ec0]);
        float2 p = upk(s);      // (col ec0, col ec0+1)

        // hprev for these columns lives in warp ns's buffer (k = nBase+ec0)
        float2 hp = *(const float2*)(sm + ns * BUF_FLOATS + er * S_BUF + ec0);

        float2 o;
        o.x = hp.x * (1.0f - ALPHA_C) + ALPHA_C * tanhf(xp.x + p.x);
        o.y = hp.y * (1.0f - ALPHA_C) + ALPHA_C * tanhf(xp.y + p.y);

        float* dst = out + (size_t)t * BN + (size_t)(bBase + er) * NN + nBase + ec0;
        __stcg((float2*)dst, o);
        if (t == TT - 1) {  // final hidden state appended after the sequence
            float* tail = out + (size_t)TT * BN + (size_t)(bBase + er) * NN + nBase + ec0;
            __stcg((float2*)tail, o);
        }

        // --- group barrier (16 CTAs sharing these batch rows), monotonic.
        // bar + single-thread release fence / arrival / acquire poll.
        __syncthreads();
        if (t < TT - 1) {
            if (tid == 0) {
                asm volatile("fence.acq_rel.gpu;" ::: "memory");
                atomicAdd(&g_bar[bg], 1u);
                const unsigned target = 16u * (unsigned)(t + 1);
                unsigned v;
                while (true) {
                    asm volatile("ld.acquire.gpu.global.u32 %0, [%1];"
                                 : "=r"(v) : "l"(&g_bar[bg]) : "memory");
                    if (v >= target) break;
                    __nanosleep(32);
                }
            }
            __syncthreads();
        }
    }
}

extern "C" void kernel_launch(void* const* d_in, const int* in_sizes, int n_in,
                              void* d_out, int out_size)
{
    (void)in_sizes; (void)n_in; (void)out_size;
    const float* x   = (const float*)d_in[0];   // [1000, 256, 128]
    const float* h0  = (const float*)d_in[1];   // [256, 512]
    const float* Win = (const float*)d_in[2];   // [512, 128]
    const float* bin = (const float*)d_in[3];   // [512]
    const float* Whh = (const float*)d_in[4];   // [512, 512]
    float* out = (float*)d_out;                 // [1000*256*512 + 256*512]

    static int smem_set = 0;
    if (!smem_set) {
        cudaFuncSetAttribute(rnn_persistent,
                             cudaFuncAttributeMaxDynamicSharedMemorySize, SMEM_BYTES);
        smem_set = 1;
    }

    // Phase 1: xproj for all timesteps -> out[t] slots (also resets g_bar).
    dim3 gA(NN / 64, (TT * BB) / 64);           // (8, 4000)
    xproj_kernel<<<gA, 256>>>(x, Win, bin, out);

    // Phase 2: persistent recurrence, 128 co-resident CTAs.
    rnn_persistent<<<GROUPS * SLICES, 512, SMEM_BYTES>>>(h0, Whh, out);
}